// round 9
// baseline (speedup 1.0000x reference)
#include <cuda_runtime.h>
#include <cuda_bf16.h>
#include <cstdint>

#define N_NODES 50000
#define N_EDGES 800000
#define DIM 64
#define HID 128
#define DT 0.1f
#define TAU 2.0f
#define LAMBDA_W 1e-4f
#define N_STEPS 10

#define PADW 68
#define NPART 196   // ceil(50000/256)

// ---------------- scratch (device globals; zero-initialized at load) ---------------
__device__ float g_x[N_NODES * DIM];
__device__ float g_e[N_NODES * DIM];
__device__ float g_msg[N_NODES * DIM];
__device__ int2  g_edge[N_EDGES];       // original order
__device__ int2  g_edge_s[N_EDGES];     // tgt-sorted
__device__ float g_ws[N_EDGES];         // tgt-sorted weights
__device__ int   g_perm[N_EDGES];       // sorted pos -> original id
__device__ int   g_cnt[N_NODES];        // histogram (zeroed by finalize)
__device__ int   g_fill[N_NODES];       // scatter counters (zeroed by finalize)
__device__ int   g_intra[N_NODES];      // exclusive prefix within 256-chunk
__device__ int   g_partial[256];        // per-chunk totals
__device__ int   g_blockoff[256];       // exclusive prefix of chunk totals
__device__ uint32_t g_w1t[2 * HID * PADW];
__device__ uint32_t g_w2t[2 * DIM * PADW];

__device__ __forceinline__ void split2(float v, __nv_bfloat16& h, __nv_bfloat16& l) {
    h = __float2bfloat16_rn(v);
    l = __float2bfloat16_rn(v - __bfloat162float(h));
}
__device__ __forceinline__ uint32_t pack2(__nv_bfloat16 a, __nv_bfloat16 b) {
    __nv_bfloat162 t = __halves2bfloat162(a, b);
    return *(uint32_t*)&t;
}
__device__ __forceinline__ void mma_bf16(float c[4], uint32_t a0, uint32_t a1,
                                         uint32_t a2, uint32_t a3,
                                         uint32_t b0, uint32_t b1) {
    asm volatile(
        "mma.sync.aligned.m16n8k16.row.col.f32.bf16.bf16.f32 "
        "{%0,%1,%2,%3}, {%4,%5,%6,%7}, {%8,%9}, {%0,%1,%2,%3};"
        : "+f"(c[0]), "+f"(c[1]), "+f"(c[2]), "+f"(c[3])
        : "r"(a0), "r"(a1), "r"(a2), "r"(a3), "r"(b0), "r"(b1));
}

// ---------------- launch 0: convert + init + histogram -----------------------------
__global__ void convert_init_kernel(const void* __restrict__ ei,
                                    const float* __restrict__ x_in) {
    __shared__ int s_is64;
    if (threadIdx.x < 32) {
        int v = ((const int*)ei)[2 * threadIdx.x + 1];
        unsigned nz = __ballot_sync(0xffffffffu, v != 0);
        if (threadIdx.x == 0) s_is64 = (nz == 0u) ? 1 : 0;
    }
    __syncthreads();
    int i = blockIdx.x * blockDim.x + threadIdx.x;
    if (i < N_EDGES) {
        int s, t;
        if (s_is64) {
            const long long* p = (const long long*)ei;
            s = (int)p[i];
            t = (int)p[N_EDGES + i];
        } else {
            const int* p = (const int*)ei;
            s = p[i];
            t = p[N_EDGES + i];
        }
        g_edge[i] = make_int2(s, t);
        atomicAdd(&g_cnt[t], 1);
    }
    if (i < N_NODES * DIM) {
        g_x[i] = x_in[i];
        g_e[i] = 0.0f;
        g_msg[i] = 0.0f;
    }
}

// ---------------- launch 1: per-256-chunk exclusive scan ---------------------------
__global__ void __launch_bounds__(256) scan_partial_kernel() {
    __shared__ int s[256];
    int tid = threadIdx.x;
    int i = blockIdx.x * 256 + tid;
    int v = (i < N_NODES) ? g_cnt[i] : 0;
    s[tid] = v;
    __syncthreads();
#pragma unroll
    for (int off = 1; off < 256; off <<= 1) {
        int t = (tid >= off) ? s[tid - off] : 0;
        __syncthreads();
        s[tid] += t;
        __syncthreads();
    }
    if (i < N_NODES) g_intra[i] = s[tid] - v;   // exclusive
    if (tid == 255) g_partial[blockIdx.x] = s[255];
}

// ---------------- launch 2: scan chunk totals --------------------------------------
__global__ void __launch_bounds__(256) scan_top_kernel() {
    __shared__ int s[256];
    int tid = threadIdx.x;
    int v = (tid < NPART) ? g_partial[tid] : 0;
    s[tid] = v;
    __syncthreads();
#pragma unroll
    for (int off = 1; off < 256; off <<= 1) {
        int t = (tid >= off) ? s[tid - off] : 0;
        __syncthreads();
        s[tid] += t;
        __syncthreads();
    }
    if (tid < NPART) g_blockoff[tid] = s[tid] - v;
}

// ---------------- launch 3 (profiled): counting-sort scatter -----------------------
__global__ void scatter_kernel(const float* __restrict__ w_in) {
    int i = blockIdx.x * blockDim.x + threadIdx.x;
    if (i >= N_EDGES) return;
    int2 st = g_edge[i];
    int t = st.y;
    int pos = g_blockoff[t >> 8] + g_intra[t] + atomicAdd(&g_fill[t], 1);
    g_edge_s[pos] = st;
    g_ws[pos] = w_in[i];
    g_perm[pos] = i;
}

// ---------------- one-time weight prep (bf16 split, transposed, padded) ------------
__global__ void prep_weights_kernel(const float* __restrict__ W1,
                                    const float* __restrict__ W2) {
    int i = blockIdx.x * blockDim.x + threadIdx.x;
    if (i < HID * (HID / 2)) {
        int n = i >> 6, kp = i & 63;
        float v0 = W1[(2 * kp) * HID + n];
        float v1 = W1[(2 * kp + 1) * HID + n];
        __nv_bfloat16 h0, l0, h1, l1;
        split2(v0, h0, l0);
        split2(v1, h1, l1);
        g_w1t[n * PADW + kp] = pack2(h0, h1);
        g_w1t[HID * PADW + n * PADW + kp] = pack2(l0, l1);
    } else if (i < HID * (HID / 2) + DIM * (HID / 2)) {
        int j = i - HID * (HID / 2);
        int n = j >> 6, kp = j & 63;
        float v0 = W2[(2 * kp) * DIM + n];
        float v1 = W2[(2 * kp + 1) * DIM + n];
        __nv_bfloat16 h0, l0, h1, l1;
        split2(v0, h0, l0);
        split2(v1, h1, l1);
        g_w2t[n * PADW + kp] = pack2(h0, h1);
        g_w2t[DIM * PADW + n * PADW + kp] = pack2(l0, l1);
    }
}

// ---------------- fused edge kernel over tgt-sorted edges --------------------------
template <bool PLAST, bool MSG>
__global__ void __launch_bounds__(256) edge_kernel(const float* __restrict__ etap,
                                                   const float* __restrict__ etam) {
    int gt = blockIdx.x * 256 + threadIdx.x;
    int eidx = gt >> 4;
    int sub = gt & 15;

    int2 st = g_edge_s[eidx];
    float w = g_ws[eidx];
    const float4* x4 = (const float4*)g_x;
    float4 xs = x4[st.x * 16 + sub];
    float wn = w;

    if (PLAST) {
        const float4* e4 = (const float4*)g_e;
        float4 xt = x4[st.y * 16 + sub];       // L1-resident (sorted by tgt)
        float4 es = e4[st.x * 16 + sub];
        float4 et = e4[st.y * 16 + sub];       // L1-resident
        float pp = xs.x * et.x + xs.y * et.y + xs.z * et.z + xs.w * et.w;
        float pm = xt.x * es.x + xt.y * es.y + xt.z * es.z + xt.w * es.w;
#pragma unroll
        for (int o = 8; o > 0; o >>= 1) {
            pp += __shfl_xor_sync(0xffffffffu, pp, o);
            pm += __shfl_xor_sync(0xffffffffu, pm, o);
        }
        float ep = __ldg(etap);
        float em = __ldg(etam);
        wn = w + DT * (ep * pp - em * pm - LAMBDA_W * w);
        if (sub == 0) g_ws[eidx] = wn;
    }

    if (MSG) {
        float* dst = &g_msg[st.y * DIM + sub * 4];
        asm volatile("red.global.add.v4.f32 [%0], {%1,%2,%3,%4};"
                     :: "l"(dst), "f"(wn * xs.x), "f"(wn * xs.y),
                        "f"(wn * xs.z), "f"(wn * xs.w)
                     : "memory");
    }
}

// ---------------- bf16-split MMA node kernel (R8-proven) ---------------------------
#define NT 128
#define NTH 512
#define SW1 0
#define SW2 (SW1 + 2 * HID * PADW)
#define SAH (SW2 + 2 * DIM * PADW)
#define SB1 (SAH + 2 * NT * PADW)
#define SB2 (SB1 + HID)
#define SMEM_U32 (SB2 + DIM)
#define SMEM_BYTES (SMEM_U32 * 4)

__global__ void __launch_bounds__(NTH, 1) node_kernel(const float* __restrict__ b1,
                                                      const float* __restrict__ b2) {
    extern __shared__ uint32_t smu[];
    uint32_t* sW1 = smu + SW1;
    uint32_t* sW2 = smu + SW2;
    uint32_t* sAH = smu + SAH;
    float* sB1 = (float*)(smu + SB1);
    float* sB2 = (float*)(smu + SB2);

    int tid = threadIdx.x;
    int base = blockIdx.x * NT;

    {
        const uint4* s = (const uint4*)g_w1t;
        uint4* d = (uint4*)sW1;
        for (int i = tid; i < (2 * HID * PADW) / 4; i += NTH) d[i] = s[i];
        const uint4* s2 = (const uint4*)g_w2t;
        uint4* d2 = (uint4*)sW2;
        for (int i = tid; i < (2 * DIM * PADW) / 4; i += NTH) d2[i] = s2[i];
    }
    if (tid < HID) sB1[tid] = b1[tid];
    if (tid >= HID && tid < HID + DIM) sB2[tid - HID] = b2[tid - HID];

    for (int p = tid; p < NT * (HID / 2); p += NTH) {
        int r = p >> 6, cp = p & 63;
        int c = 2 * cp;
        int node = base + r;
        float v0 = 0.f, v1 = 0.f;
        if (node < N_NODES) {
            if (c < DIM) {
                v0 = g_x[node * DIM + c];
                v1 = g_x[node * DIM + c + 1];
            } else {
                v0 = g_msg[node * DIM + c - DIM];
                v1 = g_msg[node * DIM + c - DIM + 1];
            }
        }
        __nv_bfloat16 h0, l0, h1, l1;
        split2(v0, h0, l0);
        split2(v1, h1, l1);
        sAH[r * PADW + cp] = pack2(h0, h1);
        sAH[NT * PADW + r * PADW + cp] = pack2(l0, l1);
    }
    __syncthreads();

    int wid = tid >> 5;
    int lane = tid & 31;
    int rg = wid & 7;
    int nh = wid >> 3;
    int grp = lane >> 2;
    int qt = lane & 3;
    int r0 = 16 * rg + grp;

    float c1[8][4];
#pragma unroll
    for (int nt = 0; nt < 8; nt++) {
        int col0 = 64 * nh + 8 * nt + 2 * qt;
        c1[nt][0] = sB1[col0];
        c1[nt][1] = sB1[col0 + 1];
        c1[nt][2] = c1[nt][0];
        c1[nt][3] = c1[nt][1];
    }
#pragma unroll
    for (int kk = 0; kk < 8; kk++) {
        int wc0 = 8 * kk + qt;
        int wc1 = wc0 + 4;
        uint32_t ah0 = sAH[r0 * PADW + wc0];
        uint32_t ah1 = sAH[(r0 + 8) * PADW + wc0];
        uint32_t ah2 = sAH[r0 * PADW + wc1];
        uint32_t ah3 = sAH[(r0 + 8) * PADW + wc1];
        uint32_t al0 = sAH[NT * PADW + r0 * PADW + wc0];
        uint32_t al1 = sAH[NT * PADW + (r0 + 8) * PADW + wc0];
        uint32_t al2 = sAH[NT * PADW + r0 * PADW + wc1];
        uint32_t al3 = sAH[NT * PADW + (r0 + 8) * PADW + wc1];
#pragma unroll
        for (int nt = 0; nt < 8; nt++) {
            int n = 64 * nh + 8 * nt + grp;
            uint32_t bh0 = sW1[n * PADW + wc0];
            uint32_t bh1 = sW1[n * PADW + wc1];
            uint32_t bl0 = sW1[HID * PADW + n * PADW + wc0];
            uint32_t bl1 = sW1[HID * PADW + n * PADW + wc1];
            mma_bf16(c1[nt], ah0, ah1, ah2, ah3, bh0, bh1);
            mma_bf16(c1[nt], ah0, ah1, ah2, ah3, bl0, bl1);
            mma_bf16(c1[nt], al0, al1, al2, al3, bh0, bh1);
        }
    }
    __syncthreads();

#pragma unroll
    for (int nt = 0; nt < 8; nt++) {
        int wcol = 32 * nh + 4 * nt + qt;
        float f0 = fmaxf(c1[nt][0], 0.f), f1 = fmaxf(c1[nt][1], 0.f);
        float f2 = fmaxf(c1[nt][2], 0.f), f3 = fmaxf(c1[nt][3], 0.f);
        __nv_bfloat16 h0, l0, h1, l1, h2, l2, h3, l3;
        split2(f0, h0, l0); split2(f1, h1, l1);
        split2(f2, h2, l2); split2(f3, h3, l3);
        sAH[r0 * PADW + wcol] = pack2(h0, h1);
        sAH[NT * PADW + r0 * PADW + wcol] = pack2(l0, l1);
        sAH[(r0 + 8) * PADW + wcol] = pack2(h2, h3);
        sAH[NT * PADW + (r0 + 8) * PADW + wcol] = pack2(l2, l3);
    }
    __syncthreads();

    float c2[4][4];
#pragma unroll
    for (int nt = 0; nt < 4; nt++) {
        int col0 = 32 * nh + 8 * nt + 2 * qt;
        c2[nt][0] = sB2[col0];
        c2[nt][1] = sB2[col0 + 1];
        c2[nt][2] = c2[nt][0];
        c2[nt][3] = c2[nt][1];
    }
#pragma unroll
    for (int kk = 0; kk < 8; kk++) {
        int wc0 = 8 * kk + qt;
        int wc1 = wc0 + 4;
        uint32_t ah0 = sAH[r0 * PADW + wc0];
        uint32_t ah1 = sAH[(r0 + 8) * PADW + wc0];
        uint32_t ah2 = sAH[r0 * PADW + wc1];
        uint32_t ah3 = sAH[(r0 + 8) * PADW + wc1];
        uint32_t al0 = sAH[NT * PADW + r0 * PADW + wc0];
        uint32_t al1 = sAH[NT * PADW + (r0 + 8) * PADW + wc0];
        uint32_t al2 = sAH[NT * PADW + r0 * PADW + wc1];
        uint32_t al3 = sAH[NT * PADW + (r0 + 8) * PADW + wc1];
#pragma unroll
        for (int nt = 0; nt < 4; nt++) {
            int n = 32 * nh + 8 * nt + grp;
            uint32_t bh0 = sW2[n * PADW + wc0];
            uint32_t bh1 = sW2[n * PADW + wc1];
            uint32_t bl0 = sW2[DIM * PADW + n * PADW + wc0];
            uint32_t bl1 = sW2[DIM * PADW + n * PADW + wc1];
            mma_bf16(c2[nt], ah0, ah1, ah2, ah3, bh0, bh1);
            mma_bf16(c2[nt], ah0, ah1, ah2, ah3, bl0, bl1);
            mma_bf16(c2[nt], al0, al1, al2, al3, bh0, bh1);
        }
    }

#pragma unroll
    for (int nt = 0; nt < 4; nt++) {
        int col0 = 32 * nh + 8 * nt + 2 * qt;
#pragma unroll
        for (int half = 0; half < 2; half++) {
            int node = base + r0 + 8 * half;
            if (node < N_NODES) {
                int gi = node * DIM + col0;
                float f0 = c2[nt][2 * half];
                float f1 = c2[nt][2 * half + 1];
                float2 xv = *(float2*)&g_x[gi];
                float2 xn = make_float2(xv.x + DT * (f0 - xv.x),
                                        xv.y + DT * (f1 - xv.y));
                *(float2*)&g_x[gi] = xn;
                float2 ev = *(float2*)&g_e[gi];
                ev.x = ev.x + DT * (xn.x - ev.x * (1.0f / TAU));
                ev.y = ev.y + DT * (xn.y - ev.y * (1.0f / TAU));
                *(float2*)&g_e[gi] = ev;
                *(float2*)&g_msg[gi] = make_float2(0.f, 0.f);
            }
        }
    }
}

// ---------------- finalize: output + reset histogram/fill for next launch ----------
__global__ void finalize_kernel(float* __restrict__ out) {
    int i = blockIdx.x * blockDim.x + threadIdx.x;
    if (i < N_NODES * DIM) {
        out[i] = g_x[i];
    } else if (i < N_NODES * DIM + N_EDGES) {
        int j = i - N_NODES * DIM;
        out[N_NODES * DIM + g_perm[j]] = g_ws[j];
    }
    if (i < N_NODES) {
        g_cnt[i] = 0;
        g_fill[i] = 0;
    }
}

// ---------------- launch ------------------------------------------------------------
extern "C" void kernel_launch(void* const* d_in, const int* in_sizes, int n_in,
                              void* d_out, int out_size) {
    const float* x_in  = (const float*)d_in[0];
    const void*  ei    = d_in[1];
    const float* ea    = (const float*)d_in[2];
    const float* etap  = (const float*)d_in[3];
    const float* etam  = (const float*)d_in[4];
    const float* W1    = (const float*)d_in[5];
    const float* b1    = (const float*)d_in[6];
    const float* W2    = (const float*)d_in[7];
    const float* b2    = (const float*)d_in[8];

    cudaFuncSetAttribute(node_kernel, cudaFuncAttributeMaxDynamicSharedMemorySize,
                         SMEM_BYTES);

    const int EBLK = (N_EDGES * 16) / 256;            // 50000
    const int NBLK = (N_NODES + NT - 1) / NT;         // 391
    const int PREP = HID * (HID / 2) + DIM * (HID / 2);

    convert_init_kernel<<<(N_NODES * DIM + 255) / 256, 256>>>(ei, x_in);   // 0
    scan_partial_kernel<<<NPART, 256>>>();                                  // 1
    scan_top_kernel<<<1, 256>>>();                                          // 2
    scatter_kernel<<<(N_EDGES + 255) / 256, 256>>>(ea);                     // 3 (profiled)
    prep_weights_kernel<<<(PREP + 255) / 256, 256>>>(W1, W2);               // 4

    edge_kernel<false, true><<<EBLK, 256>>>(etap, etam);
    node_kernel<<<NBLK, NTH, SMEM_BYTES>>>(b1, b2);

    for (int t = 1; t < N_STEPS; t++) {
        edge_kernel<true, true><<<EBLK, 256>>>(etap, etam);
        node_kernel<<<NBLK, NTH, SMEM_BYTES>>>(b1, b2);
    }
    edge_kernel<true, false><<<EBLK, 256>>>(etap, etam);

    finalize_kernel<<<(N_NODES * DIM + N_EDGES + 255) / 256, 256>>>((float*)d_out);
}